// round 5
// baseline (speedup 1.0000x reference)
#include <cuda_runtime.h>
#include <cuda_fp16.h>
#include <cstdint>

// Problem constants
#define NN 50000
#define EE 1600000
#define K0 319999u     // floor(0.2*(E-1)) rank (ascending, 0-based)
#define K1 320000u
#define EPS 1e-16f
#define CAP 4096

// ---------------- device scratch (static, no allocation) ----------------
__device__ unsigned g_hist16[65536];
__device__ unsigned g_binid[2];
__device__ unsigned g_cumbefore[2];
__device__ unsigned g_cand_cnt[2];
__device__ float    g_cand[2][CAP];
__device__ float    g_thr;

__device__ float    g_attsums[NN];
__device__ unsigned g_deg[NN];
__device__ unsigned g_rowstart[NN + 1];
__device__ unsigned g_cursor[NN];
__device__ __align__(16)  int2   g_edges[EE];   // (src, bitcast(w)) for KEPT edges only

__device__ __align__(256) float  g_Y1[NN * 64];
__device__ __align__(256) float  g_Y2[NN * 64];
__device__ __align__(256) float  g_S [NN * 64];
__device__ __align__(256) __half g_H0[NN * 64]; // fp16 gather shadows (ping-pong)
__device__ __align__(256) __half g_H1[NN * 64];

// ---------------- zero ----------------
__global__ void k_zero() {
    int i = blockIdx.x * blockDim.x + threadIdx.x;
    if (i < 65536) g_hist16[i] = 0u;
    if (i < NN) { g_attsums[i] = 0.f; g_deg[i] = 0u; }
    if (i < 2) g_cand_cnt[i] = 0u;
}

// ---------------- quantile: 16-bit histogram (single full pass) ----------------
// att in [0,1): positive floats, uint bit pattern order-isomorphic to value.
__global__ void k_hist16(const float4* __restrict__ att4) {
    int stride = gridDim.x * blockDim.x;
    for (int i = blockIdx.x * blockDim.x + threadIdx.x; i < EE / 4; i += stride) {
        float4 v = att4[i];
        atomicAdd(&g_hist16[__float_as_uint(v.x) >> 16], 1u);
        atomicAdd(&g_hist16[__float_as_uint(v.y) >> 16], 1u);
        atomicAdd(&g_hist16[__float_as_uint(v.z) >> 16], 1u);
        atomicAdd(&g_hist16[__float_as_uint(v.w) >> 16], 1u);
    }
}

// scan 65536 bins with one block; find bins containing ranks K0, K1
__global__ void k_scan16() {
    __shared__ unsigned ps[1024];
    int t = threadIdx.x;
    unsigned base = t * 64u;
    unsigned sum = 0;
    #pragma unroll 8
    for (int i = 0; i < 64; i++) sum += g_hist16[base + i];
    ps[t] = sum;
    __syncthreads();
    for (int off = 1; off < 1024; off <<= 1) {
        unsigned v = (t >= off) ? ps[t - off] : 0u;
        __syncthreads();
        ps[t] += v;
        __syncthreads();
    }
    unsigned run = ps[t] - sum;   // exclusive prefix of this chunk
    for (int i = 0; i < 64; i++) {
        unsigned c = g_hist16[base + i];
        if (c) {
            if (K0 >= run && K0 < run + c) { g_binid[0] = base + i; g_cumbefore[0] = run; }
            if (K1 >= run && K1 < run + c) { g_binid[1] = base + i; g_cumbefore[1] = run; }
        }
        run += c;
    }
}

// collect candidate values whose hi-16 bits match the target bin(s)
__global__ void k_collect(const float4* __restrict__ att4) {
    unsigned b0 = g_binid[0], b1 = g_binid[1];
    int stride = gridDim.x * blockDim.x;
    for (int i = blockIdx.x * blockDim.x + threadIdx.x; i < EE / 4; i += stride) {
        float4 v = att4[i];
        float a[4] = {v.x, v.y, v.z, v.w};
        #pragma unroll
        for (int j = 0; j < 4; j++) {
            unsigned hi = __float_as_uint(a[j]) >> 16;
            if (hi == b0) {
                unsigned p = atomicAdd(&g_cand_cnt[0], 1u);
                if (p < CAP) g_cand[0][p] = a[j];
            } else if (hi == b1) {
                unsigned p = atomicAdd(&g_cand_cnt[1], 1u);
                if (p < CAP) g_cand[1][p] = a[j];
            }
        }
    }
}

// exact order statistics via 2x 8-bit in-smem radix refinement (reconstructs bits)
__global__ void k_select() {
    __shared__ unsigned skey[CAP];
    __shared__ unsigned h[257];
    __shared__ unsigned sb1, srank2, sb0;
    __shared__ float vsel[2];
    int t = threadIdx.x;
    unsigned b0id = g_binid[0], b1id = g_binid[1];

    for (int sel = 0; sel < 2; sel++) {
        int bufi = (sel == 1 && b1id != b0id) ? 1 : 0;
        unsigned bin = (sel == 0) ? b0id : b1id;
        unsigned rank = ((sel == 0) ? K0 : K1) - g_cumbefore[sel];
        unsigned n = min(g_cand_cnt[bufi], (unsigned)CAP);

        for (int i = t; i < CAP; i += 1024)
            skey[i] = (i < (int)n) ? __float_as_uint(g_cand[bufi][i]) : 0xFFFFFFFFu;
        if (t < 257) h[t] = 0u;
        __syncthreads();

        // pass on byte1 (bits 15:8)
        for (int i = t; i < (int)n; i += 1024) atomicAdd(&h[(skey[i] >> 8) & 255u], 1u);
        __syncthreads();
        if (t == 0) { unsigned run = 0; for (int b = 0; b < 256; b++) { unsigned c = h[b]; h[b] = run; run += c; } h[256] = run; }
        __syncthreads();
        if (t < 256 && h[t] <= rank && rank < h[t + 1]) { sb1 = t; srank2 = rank - h[t]; }
        __syncthreads();
        unsigned mb1 = sb1, r2 = srank2;
        if (t < 257) h[t] = 0u;
        __syncthreads();

        // pass on byte0 (bits 7:0) among matching byte1
        for (int i = t; i < (int)n; i += 1024) {
            unsigned k = skey[i];
            if (((k >> 8) & 255u) == mb1) atomicAdd(&h[k & 255u], 1u);
        }
        __syncthreads();
        if (t == 0) { unsigned run = 0; for (int b = 0; b < 256; b++) { unsigned c = h[b]; h[b] = run; run += c; } h[256] = run; }
        __syncthreads();
        if (t < 256 && h[t] <= r2 && r2 < h[t + 1]) sb0 = t;
        __syncthreads();

        if (t == 0) vsel[sel] = __uint_as_float((bin << 16) | (mb1 << 8) | sb0);
        __syncthreads();
    }
    if (t == 0) g_thr = vsel[0] + 0.8f * (vsel[1] - vsel[0]);
}

// ---------------- kept-edge pass: att_sums over src + degree over dst ----------------
__global__ void k_edge2(const float* __restrict__ att,
                        const int* __restrict__ src,
                        const int* __restrict__ dst) {
    int e = blockIdx.x * blockDim.x + threadIdx.x;
    if (e >= EE) return;
    float a = att[e];
    if (a > g_thr) {
        atomicAdd(&g_attsums[src[e]], a);
        atomicAdd(&g_deg[dst[e]], 1u);
    }
}

// ---------------- exclusive prefix over degrees (single block) ----------------
__global__ void k_scanDeg() {
    __shared__ unsigned ps[1024];
    const int C = 49;                     // 1024*49 >= 50000
    int t = threadIdx.x;
    int base = t * C;
    unsigned sum = 0;
    for (int i = 0; i < C; i++) {
        int j = base + i;
        if (j < NN) sum += g_deg[j];
    }
    ps[t] = sum;
    __syncthreads();
    for (int off = 1; off < 1024; off <<= 1) {
        unsigned v = (t >= off) ? ps[t - off] : 0u;
        __syncthreads();
        ps[t] += v;
        __syncthreads();
    }
    unsigned run = ps[t] - sum;
    for (int i = 0; i < C; i++) {
        int j = base + i;
        if (j < NN) {
            g_rowstart[j] = run;
            g_cursor[j]   = run;
            run += g_deg[j];
        }
    }
    if (t == 1023) g_rowstart[NN] = ps[1023];
}

// ---------------- scatter KEPT edges into dst-sorted CSR with weights ----------------
__global__ void k_scatter(const float* __restrict__ att,
                          const int* __restrict__ src,
                          const int* __restrict__ dst) {
    int e = blockIdx.x * blockDim.x + threadIdx.x;
    if (e >= EE) return;
    float a = att[e];
    if (a <= g_thr) return;
    int s = src[e];
    int d = dst[e];
    float w = a / (g_attsums[s] + EPS);
    unsigned pos = atomicAdd(&g_cursor[d], 1u);
    g_edges[pos] = make_int2(s, __float_as_int(w));
}

// ---------------- x -> fp16 shadow ----------------
__global__ void k_xcvt(const float2* __restrict__ x) {
    int i = blockIdx.x * blockDim.x + threadIdx.x;
    if (i < NN * 32) {
        float2 v = x[i];
        ((__half2*)g_H0)[i] = __floats2half2_rn(v.x, v.y);
    }
}

// ---------------- fused RK4 stage ----------------
// MODE 1: gather H0(x);  yrow=x;  S  = k;   Y1 = x+0.5k; H1 = half(Y1)
// MODE 2: gather H1(y1); yrow=Y1; S += 2k;  Y2 = x+0.5k; H0 = half(Y2)
// MODE 3: gather H0(y2); yrow=Y2; S += 2k;  Y1 = x+k;    H1 = half(Y1)
// MODE 4: gather H1(y3); yrow=Y1; out = x + (S + k)/6
template <int MODE>
__global__ void k_stage(const float2* __restrict__ x, float2* __restrict__ out) {
    int gw   = (blockIdx.x * blockDim.x + threadIdx.x) >> 5;
    int lane = threadIdx.x & 31;
    if (gw >= NN) return;

    const __half2* __restrict__ Hin =
        (MODE == 1 || MODE == 3) ? (const __half2*)g_H0 : (const __half2*)g_H1;

    unsigned e0 = g_rowstart[gw];
    unsigned e1 = g_rowstart[gw + 1];

    float ax = 0.f, ay = 0.f, bx = 0.f, by = 0.f;
    unsigned e = e0;
    for (; e + 4 <= e1; e += 4) {
        int2 p0 = __ldg(&g_edges[e]);
        int2 p1 = __ldg(&g_edges[e + 1]);
        int2 p2 = __ldg(&g_edges[e + 2]);
        int2 p3 = __ldg(&g_edges[e + 3]);
        float2 f0 = __half22float2(__ldg(&Hin[p0.x * 32 + lane]));
        float2 f1 = __half22float2(__ldg(&Hin[p1.x * 32 + lane]));
        float2 f2 = __half22float2(__ldg(&Hin[p2.x * 32 + lane]));
        float2 f3 = __half22float2(__ldg(&Hin[p3.x * 32 + lane]));
        float w0 = __int_as_float(p0.y), w1 = __int_as_float(p1.y);
        float w2 = __int_as_float(p2.y), w3 = __int_as_float(p3.y);
        ax = fmaf(w0, f0.x, ax); ay = fmaf(w0, f0.y, ay);
        bx = fmaf(w1, f1.x, bx); by = fmaf(w1, f1.y, by);
        ax = fmaf(w2, f2.x, ax); ay = fmaf(w2, f2.y, ay);
        bx = fmaf(w3, f3.x, bx); by = fmaf(w3, f3.y, by);
    }
    for (; e < e1; e++) {
        int2 p = __ldg(&g_edges[e]);
        float2 f = __half22float2(__ldg(&Hin[p.x * 32 + lane]));
        float w = __int_as_float(p.y);
        ax = fmaf(w, f.x, ax); ay = fmaf(w, f.y, ay);
    }
    ax += bx; ay += by;

    int idx = gw * 32 + lane;
    const float2* Yin = (MODE == 1) ? x
                      : (MODE == 2) ? (const float2*)g_Y1
                      : (MODE == 3) ? (const float2*)g_Y2
                                    : (const float2*)g_Y1;
    float2 yr = Yin[idx];
    float kx = ax - yr.x;
    float ky = ay - yr.y;
    float2 xr = (MODE == 1) ? yr : x[idx];
    float2* S2 = (float2*)g_S;

    if (MODE == 1) {
        S2[idx] = make_float2(kx, ky);
        float nx = xr.x + 0.5f * kx, ny = xr.y + 0.5f * ky;
        ((float2*)g_Y1)[idx] = make_float2(nx, ny);
        ((__half2*)g_H1)[idx] = __floats2half2_rn(nx, ny);
    } else if (MODE == 2) {
        float2 s = S2[idx];
        S2[idx] = make_float2(s.x + 2.f * kx, s.y + 2.f * ky);
        float nx = xr.x + 0.5f * kx, ny = xr.y + 0.5f * ky;
        ((float2*)g_Y2)[idx] = make_float2(nx, ny);
        ((__half2*)g_H0)[idx] = __floats2half2_rn(nx, ny);
    } else if (MODE == 3) {
        float2 s = S2[idx];
        S2[idx] = make_float2(s.x + 2.f * kx, s.y + 2.f * ky);
        float nx = xr.x + kx, ny = xr.y + ky;
        ((float2*)g_Y1)[idx] = make_float2(nx, ny);
        ((__half2*)g_H1)[idx] = __floats2half2_rn(nx, ny);
    } else {
        float2 s = S2[idx];
        const float c = 1.f / 6.f;
        out[idx] = make_float2(xr.x + (s.x + kx) * c, xr.y + (s.y + ky) * c);
    }
}

// ---------------- launch ----------------
extern "C" void kernel_launch(void* const* d_in, const int* in_sizes, int n_in,
                              void* d_out, int out_size) {
    const float* x   = (const float*)d_in[0];   // [50000, 64]
    const float* att = (const float*)d_in[1];   // [1600000, 1]
    const int*   ei  = (const int*)d_in[2];     // [2, 1600000]
    const int* src = ei;
    const int* dst = ei + EE;
    float* out = (float*)d_out;

    const int T = 256;
    const int eb = (EE + T - 1) / T;            // 6250
    const int sb = (NN * 32 + T - 1) / T;       // 6250 (warp per row)

    k_zero<<<256, T>>>();
    k_hist16<<<1024, T>>>((const float4*)att);
    k_scan16<<<1, 1024>>>();
    k_collect<<<1024, T>>>((const float4*)att);
    k_select<<<1, 1024>>>();
    k_edge2<<<eb, T>>>(att, src, dst);
    k_scanDeg<<<1, 1024>>>();
    k_scatter<<<eb, T>>>(att, src, dst);
    k_xcvt<<<sb, T>>>((const float2*)x);

    k_stage<1><<<sb, T>>>((const float2*)x, (float2*)out);
    k_stage<2><<<sb, T>>>((const float2*)x, (float2*)out);
    k_stage<3><<<sb, T>>>((const float2*)x, (float2*)out);
    k_stage<4><<<sb, T>>>((const float2*)x, (float2*)out);
}

// round 6
// speedup vs baseline: 1.0177x; 1.0177x over previous
#include <cuda_runtime.h>
#include <cstdint>

// Problem constants
#define NN 50000
#define EE 1600000
#define D2 32          // float2 columns per row
#define K0 319999u     // floor(0.2*(E-1)) rank (ascending, 0-based)
#define K1 320000u
#define EPS 1e-16f
#define CAP 4096

// ---------------- device scratch (static, no allocation) ----------------
__device__ unsigned g_hist16[65536];
__device__ unsigned g_binid[2];
__device__ unsigned g_cumbefore[2];
__device__ unsigned g_cand_cnt[2];
__device__ float    g_cand[2][CAP];
__device__ float    g_thr;

__device__ float    g_attsums[NN];
__device__ unsigned g_deg[NN];
__device__ unsigned g_rowstart[NN + 1];
__device__ unsigned g_cursor[NN];

__device__ int      g_srcs[EE];
__device__ float    g_w[EE];

__device__ __align__(256) float g_Y1[NN * 64];
__device__ __align__(256) float g_Y2[NN * 64];
__device__ __align__(256) float g_S [NN * 64];

// ---------------- zero ----------------
__global__ void k_zero() {
    int i = blockIdx.x * blockDim.x + threadIdx.x;
    if (i < 65536) g_hist16[i] = 0u;
    if (i < NN) { g_attsums[i] = 0.f; g_deg[i] = 0u; }
    if (i < 2) g_cand_cnt[i] = 0u;
}

// ---------------- quantile: 16-bit histogram (single full pass) ----------------
// att in [0,1): positive floats, uint bit pattern order-isomorphic to value.
__global__ void k_hist16(const float4* __restrict__ att4) {
    int stride = gridDim.x * blockDim.x;
    for (int i = blockIdx.x * blockDim.x + threadIdx.x; i < EE / 4; i += stride) {
        float4 v = att4[i];
        atomicAdd(&g_hist16[__float_as_uint(v.x) >> 16], 1u);
        atomicAdd(&g_hist16[__float_as_uint(v.y) >> 16], 1u);
        atomicAdd(&g_hist16[__float_as_uint(v.z) >> 16], 1u);
        atomicAdd(&g_hist16[__float_as_uint(v.w) >> 16], 1u);
    }
}

// scan 65536 bins with one block; find bins containing ranks K0, K1
__global__ void k_scan16() {
    __shared__ unsigned ps[1024];
    int t = threadIdx.x;
    unsigned base = t * 64u;
    unsigned sum = 0;
    #pragma unroll 8
    for (int i = 0; i < 64; i++) sum += g_hist16[base + i];
    ps[t] = sum;
    __syncthreads();
    for (int off = 1; off < 1024; off <<= 1) {
        unsigned v = (t >= off) ? ps[t - off] : 0u;
        __syncthreads();
        ps[t] += v;
        __syncthreads();
    }
    unsigned run = ps[t] - sum;   // exclusive prefix of this chunk
    for (int i = 0; i < 64; i++) {
        unsigned c = g_hist16[base + i];
        if (c) {
            if (K0 >= run && K0 < run + c) { g_binid[0] = base + i; g_cumbefore[0] = run; }
            if (K1 >= run && K1 < run + c) { g_binid[1] = base + i; g_cumbefore[1] = run; }
        }
        run += c;
    }
}

// collect candidate values whose hi-16 bits match the target bin(s)
__global__ void k_collect(const float4* __restrict__ att4) {
    unsigned b0 = g_binid[0], b1 = g_binid[1];
    int stride = gridDim.x * blockDim.x;
    for (int i = blockIdx.x * blockDim.x + threadIdx.x; i < EE / 4; i += stride) {
        float4 v = att4[i];
        float a[4] = {v.x, v.y, v.z, v.w};
        #pragma unroll
        for (int j = 0; j < 4; j++) {
            unsigned hi = __float_as_uint(a[j]) >> 16;
            if (hi == b0) {
                unsigned p = atomicAdd(&g_cand_cnt[0], 1u);
                if (p < CAP) g_cand[0][p] = a[j];
            } else if (hi == b1) {
                unsigned p = atomicAdd(&g_cand_cnt[1], 1u);
                if (p < CAP) g_cand[1][p] = a[j];
            }
        }
    }
}

// exact order statistics via 2x 8-bit in-smem radix refinement (reconstructs bits)
__global__ void k_select() {
    __shared__ unsigned skey[CAP];
    __shared__ unsigned h[257];
    __shared__ unsigned sb1, srank2, sb0;
    __shared__ float vsel[2];
    int t = threadIdx.x;
    unsigned b0id = g_binid[0], b1id = g_binid[1];

    for (int sel = 0; sel < 2; sel++) {
        int bufi = (sel == 1 && b1id != b0id) ? 1 : 0;
        unsigned bin = (sel == 0) ? b0id : b1id;
        unsigned rank = ((sel == 0) ? K0 : K1) - g_cumbefore[sel];
        unsigned n = min(g_cand_cnt[bufi], (unsigned)CAP);

        for (int i = t; i < CAP; i += 1024)
            skey[i] = (i < (int)n) ? __float_as_uint(g_cand[bufi][i]) : 0xFFFFFFFFu;
        if (t < 257) h[t] = 0u;
        __syncthreads();

        // pass on byte1 (bits 15:8)
        for (int i = t; i < (int)n; i += 1024) atomicAdd(&h[(skey[i] >> 8) & 255u], 1u);
        __syncthreads();
        if (t == 0) { unsigned run = 0; for (int b = 0; b < 256; b++) { unsigned c = h[b]; h[b] = run; run += c; } h[256] = run; }
        __syncthreads();
        if (t < 256 && h[t] <= rank && rank < h[t + 1]) { sb1 = t; srank2 = rank - h[t]; }
        __syncthreads();
        unsigned mb1 = sb1, r2 = srank2;
        __syncthreads();
        if (t < 257) h[t] = 0u;
        __syncthreads();

        // pass on byte0 (bits 7:0) among matching byte1
        for (int i = t; i < (int)n; i += 1024) {
            unsigned k = skey[i];
            if (((k >> 8) & 255u) == mb1) atomicAdd(&h[k & 255u], 1u);
        }
        __syncthreads();
        if (t == 0) { unsigned run = 0; for (int b = 0; b < 256; b++) { unsigned c = h[b]; h[b] = run; run += c; } h[256] = run; }
        __syncthreads();
        if (t < 256 && h[t] <= r2 && r2 < h[t + 1]) sb0 = t;
        __syncthreads();

        if (t == 0) vsel[sel] = __uint_as_float((bin << 16) | (mb1 << 8) | sb0);
        __syncthreads();
    }
    if (t == 0) g_thr = vsel[0] + 0.8f * (vsel[1] - vsel[0]);
}

// ---------------- kept-edge pass: att_sums over src + degree over dst ----------------
__global__ void k_edge2(const float* __restrict__ att,
                        const int* __restrict__ src,
                        const int* __restrict__ dst) {
    int e = blockIdx.x * blockDim.x + threadIdx.x;
    if (e >= EE) return;
    float a = att[e];
    if (a > g_thr) {
        atomicAdd(&g_attsums[src[e]], a);
        atomicAdd(&g_deg[dst[e]], 1u);
    }
}

// ---------------- exclusive prefix over degrees (single block) ----------------
__global__ void k_scanDeg() {
    __shared__ unsigned ps[1024];
    const int C = 49;                     // 1024*49 >= 50000
    int t = threadIdx.x;
    int base = t * C;
    unsigned sum = 0;
    for (int i = 0; i < C; i++) {
        int j = base + i;
        if (j < NN) sum += g_deg[j];
    }
    ps[t] = sum;
    __syncthreads();
    for (int off = 1; off < 1024; off <<= 1) {
        unsigned v = (t >= off) ? ps[t - off] : 0u;
        __syncthreads();
        ps[t] += v;
        __syncthreads();
    }
    unsigned run = ps[t] - sum;
    for (int i = 0; i < C; i++) {
        int j = base + i;
        if (j < NN) {
            g_rowstart[j] = run;
            g_cursor[j]   = run;
            run += g_deg[j];
        }
    }
    if (t == 1023) g_rowstart[NN] = ps[1023];
}

// ---------------- scatter KEPT edges into dst-sorted CSR with weights ----------------
__global__ void k_scatter(const float* __restrict__ att,
                          const int* __restrict__ src,
                          const int* __restrict__ dst) {
    int e = blockIdx.x * blockDim.x + threadIdx.x;
    if (e >= EE) return;
    float a = att[e];
    if (a <= g_thr) return;
    int s = src[e];
    int d = dst[e];
    float w = a / (g_attsums[s] + EPS);
    unsigned pos = atomicAdd(&g_cursor[d], 1u);
    g_srcs[pos] = s;
    g_w[pos] = w;
}

// ---------------- fused RK4 stage (R4-proven loop shape: fp32 float2 gather) ----------------
// MODE 1: Yin=x,  Yout=Y1, S  = k,        Yout = x + 0.5k
// MODE 2: Yin=Y1, Yout=Y2, S += 2k,       Yout = x + 0.5k
// MODE 3: Yin=Y2, Yout=Y1, S += 2k,       Yout = x + k
// MODE 4: Yin=Y1, Yout=out,               out  = x + (S + k)/6
template <int MODE>
__global__ void k_stage(const float2* __restrict__ x, float2* __restrict__ out) {
    int gw   = (blockIdx.x * blockDim.x + threadIdx.x) >> 5;
    int lane = threadIdx.x & 31;
    if (gw >= NN) return;

    const float2* Yin;
    float2* Yout;
    if (MODE == 1)      { Yin = x;                   Yout = (float2*)g_Y1; }
    else if (MODE == 2) { Yin = (const float2*)g_Y1; Yout = (float2*)g_Y2; }
    else if (MODE == 3) { Yin = (const float2*)g_Y2; Yout = (float2*)g_Y1; }
    else                { Yin = (const float2*)g_Y1; Yout = out; }

    unsigned e0 = g_rowstart[gw];
    unsigned e1 = g_rowstart[gw + 1];

    float ax = 0.f, ay = 0.f;
    for (unsigned e = e0; e < e1; e++) {
        int s = __ldg(&g_srcs[e]);
        float wt = __ldg(&g_w[e]);
        float2 y = __ldg(&Yin[s * D2 + lane]);
        ax = fmaf(wt, y.x, ax);
        ay = fmaf(wt, y.y, ay);
    }

    int idx = gw * D2 + lane;
    float2 yr = Yin[idx];
    float kx = ax - yr.x;
    float ky = ay - yr.y;
    float2 xr = (MODE == 1) ? yr : x[idx];
    float2* S2 = (float2*)g_S;

    if (MODE == 1) {
        S2[idx] = make_float2(kx, ky);
        Yout[idx] = make_float2(xr.x + 0.5f * kx, xr.y + 0.5f * ky);
    } else if (MODE == 2) {
        float2 s = S2[idx];
        S2[idx] = make_float2(s.x + 2.f * kx, s.y + 2.f * ky);
        Yout[idx] = make_float2(xr.x + 0.5f * kx, xr.y + 0.5f * ky);
    } else if (MODE == 3) {
        float2 s = S2[idx];
        S2[idx] = make_float2(s.x + 2.f * kx, s.y + 2.f * ky);
        Yout[idx] = make_float2(xr.x + kx, xr.y + ky);
    } else {
        float2 s = S2[idx];
        const float c = 1.f / 6.f;
        Yout[idx] = make_float2(xr.x + (s.x + kx) * c, xr.y + (s.y + ky) * c);
    }
}

// ---------------- launch ----------------
extern "C" void kernel_launch(void* const* d_in, const int* in_sizes, int n_in,
                              void* d_out, int out_size) {
    const float* x   = (const float*)d_in[0];   // [50000, 64]
    const float* att = (const float*)d_in[1];   // [1600000, 1]
    const int*   ei  = (const int*)d_in[2];     // [2, 1600000]
    const int* src = ei;
    const int* dst = ei + EE;
    float* out = (float*)d_out;

    const int T = 256;
    const int eb = (EE + T - 1) / T;            // 6250
    const int sb = (NN * 32 + T - 1) / T;       // 6250 (warp per row)

    k_zero<<<256, T>>>();
    k_hist16<<<1024, T>>>((const float4*)att);
    k_scan16<<<1, 1024>>>();
    k_collect<<<1024, T>>>((const float4*)att);
    k_select<<<1, 1024>>>();
    k_edge2<<<eb, T>>>(att, src, dst);
    k_scanDeg<<<1, 1024>>>();
    k_scatter<<<eb, T>>>(att, src, dst);

    k_stage<1><<<sb, T>>>((const float2*)x, (float2*)out);
    k_stage<2><<<sb, T>>>((const float2*)x, (float2*)out);
    k_stage<3><<<sb, T>>>((const float2*)x, (float2*)out);
    k_stage<4><<<sb, T>>>((const float2*)x, (float2*)out);
}

// round 7
// speedup vs baseline: 1.2446x; 1.2230x over previous
#include <cuda_runtime.h>
#include <cstdint>

// Problem constants
#define NN 50000
#define EE 1600000
#define DD 64
#define D2 32          // float2 columns per row
#define K0 319999u     // floor(0.2*(E-1))
#define K1 320000u
#define QFRAC 0.8f
#define EPS 1e-16f

// ---------------- device scratch (static, no allocation) ----------------
__device__ unsigned g_hist[2][256];
__device__ unsigned g_pref[2];
__device__ unsigned g_rank[2];
__device__ float    g_thr;

__device__ float    g_attsums[NN];
__device__ unsigned g_deg[NN];
__device__ unsigned g_rowstart[NN + 1];
__device__ unsigned g_cursor[NN];

__device__ int      g_srcs[EE];
__device__ float    g_w[EE];

__device__ float    g_Y1[NN * DD];
__device__ float    g_Y2[NN * DD];
__device__ float    g_S [NN * DD];

// ---------------- init / zero ----------------
__global__ void k_zero() {
    int i = blockIdx.x * blockDim.x + threadIdx.x;
    if (i < NN) { g_attsums[i] = 0.f; g_deg[i] = 0u; }
    if (i < 512) ((unsigned*)g_hist)[i] = 0u;
    if (i == 0) {
        g_pref[0] = 0u; g_pref[1] = 0u;
        g_rank[0] = K0; g_rank[1] = K1;
    }
}

// ---------------- radix select (4 passes of 8 bits, MSB first) ----------------
// att values are uniform [0,1): positive floats, so the uint bit pattern is
// order-isomorphic to the float value.
__global__ void k_hist(const float* __restrict__ att, int p) {
    __shared__ unsigned sh[512];
    for (int i = threadIdx.x; i < 512; i += blockDim.x) sh[i] = 0u;
    __syncthreads();
    unsigned pref0 = g_pref[0], pref1 = g_pref[1];
    int shamt = 24 - 8 * p;
    int stride = gridDim.x * blockDim.x;
    for (int e = blockIdx.x * blockDim.x + threadIdx.x; e < EE; e += stride) {
        unsigned key = __float_as_uint(att[e]);
        unsigned b = (key >> shamt) & 255u;
        if (p == 0) {
            atomicAdd(&sh[b], 1u);
            atomicAdd(&sh[256 + b], 1u);
        } else {
            unsigned hi = key >> (32 - 8 * p);
            if (hi == pref0) atomicAdd(&sh[b], 1u);
            if (hi == pref1) atomicAdd(&sh[256 + b], 1u);
        }
    }
    __syncthreads();
    for (int i = threadIdx.x; i < 512; i += blockDim.x) {
        unsigned v = sh[i];
        if (v) atomicAdd(&((unsigned*)g_hist)[i], v);
    }
}

__global__ void k_resolve(int p) {
    __shared__ unsigned s[256];
    int t = threadIdx.x;
    for (int sel = 0; sel < 2; sel++) {
        unsigned c = g_hist[sel][t];
        s[t] = c;
        __syncthreads();
        // inclusive scan (Hillis-Steele)
        for (int off = 1; off < 256; off <<= 1) {
            unsigned v = (t >= off) ? s[t - off] : 0u;
            __syncthreads();
            s[t] += v;
            __syncthreads();
        }
        unsigned cum  = s[t];
        unsigned rank = g_rank[sel];       // snapshot BEFORE any write
        unsigned pref = g_pref[sel];
        __syncthreads();                   // all reads done before the write below
        if (rank < cum && rank >= cum - c) {
            g_pref[sel] = (pref << 8) | (unsigned)t;
            g_rank[sel] = rank - (cum - c);
        }
        g_hist[sel][t] = 0u;               // ready for next pass
        __syncthreads();
    }
    if (p == 3 && t == 0) {
        float v0 = __uint_as_float(g_pref[0]);
        float v1 = __uint_as_float(g_pref[1]);
        g_thr = v0 + QFRAC * (v1 - v0);
    }
}

// ---------------- edge pass 1: att_sums over src + degree over dst (KEPT only) ----------------
__global__ void k_edge1(const float* __restrict__ att,
                        const int* __restrict__ src,
                        const int* __restrict__ dst) {
    int e = blockIdx.x * blockDim.x + threadIdx.x;
    if (e >= EE) return;
    float thr = g_thr;
    float a = att[e];
    if (a > thr) {
        atomicAdd(&g_attsums[src[e]], a);
        atomicAdd(&g_deg[dst[e]], 1u);
    }
}

// ---------------- exclusive prefix over degrees (single block) ----------------
__global__ void k_scan() {
    __shared__ unsigned ps[1024];
    const int C = 49;                     // 1024*49 >= 50000
    int t = threadIdx.x;
    int base = t * C;
    unsigned sum = 0;
    #pragma unroll 7
    for (int i = 0; i < C; i++) {
        int j = base + i;
        if (j < NN) sum += g_deg[j];
    }
    ps[t] = sum;
    __syncthreads();
    for (int off = 1; off < 1024; off <<= 1) {
        unsigned v = (t >= off) ? ps[t - off] : 0u;
        __syncthreads();
        ps[t] += v;
        __syncthreads();
    }
    unsigned run = (t == 0) ? 0u : ps[t - 1];
    for (int i = 0; i < C; i++) {
        int j = base + i;
        if (j < NN) {
            g_rowstart[j] = run;
            g_cursor[j]   = run;
            run += g_deg[j];
        }
    }
    if (t == 1023) g_rowstart[NN] = ps[1023];
}

// ---------------- scatter KEPT edges into dst-sorted CSR, with weights ----------------
__global__ void k_scatter(const float* __restrict__ att,
                          const int* __restrict__ src,
                          const int* __restrict__ dst) {
    int e = blockIdx.x * blockDim.x + threadIdx.x;
    if (e >= EE) return;
    float thr = g_thr;
    float a = att[e];
    if (a <= thr) return;
    int s = src[e];
    int d = dst[e];
    float w = a / (g_attsums[s] + EPS);
    unsigned pos = atomicAdd(&g_cursor[d], 1u);
    g_srcs[pos] = s;
    g_w[pos] = w;
}

// ---------------- fused RK4 stage: az = A*Yin; k = az - Yin; S update; Yout ----------------
// MODE 1: Yin=x,  Yout=Y1, S  = k,        Yout = x + 0.5k
// MODE 2: Yin=Y1, Yout=Y2, S += 2k,       Yout = x + 0.5k
// MODE 3: Yin=Y2, Yout=Y1, S += 2k,       Yout = x + k
// MODE 4: Yin=Y1, Yout=out,               out  = x + (S + k)/6
template <int MODE>
__global__ void k_stage(const float2* __restrict__ x, float2* __restrict__ out) {
    int gw   = (blockIdx.x * blockDim.x + threadIdx.x) >> 5;
    int lane = threadIdx.x & 31;
    if (gw >= NN) return;

    const float2* Yin;
    float2* Yout;
    if (MODE == 1)      { Yin = x;                   Yout = (float2*)g_Y1; }
    else if (MODE == 2) { Yin = (const float2*)g_Y1; Yout = (float2*)g_Y2; }
    else if (MODE == 3) { Yin = (const float2*)g_Y2; Yout = (float2*)g_Y1; }
    else                { Yin = (const float2*)g_Y1; Yout = out; }

    unsigned e0 = g_rowstart[gw];
    unsigned e1 = g_rowstart[gw + 1];

    float ax = 0.f, ay = 0.f;
    for (unsigned e = e0; e < e1; e++) {
        int s = __ldg(&g_srcs[e]);
        float wt = __ldg(&g_w[e]);
        float2 y = __ldg(&Yin[s * D2 + lane]);
        ax = fmaf(wt, y.x, ax);
        ay = fmaf(wt, y.y, ay);
    }

    int idx = gw * D2 + lane;
    float2 yr = Yin[idx];
    float kx = ax - yr.x;
    float ky = ay - yr.y;
    float2 xr = x[idx];
    float2* S2 = (float2*)g_S;

    if (MODE == 1) {
        S2[idx] = make_float2(kx, ky);
        Yout[idx] = make_float2(xr.x + 0.5f * kx, xr.y + 0.5f * ky);
    } else if (MODE == 2) {
        float2 s = S2[idx];
        S2[idx] = make_float2(s.x + 2.f * kx, s.y + 2.f * ky);
        Yout[idx] = make_float2(xr.x + 0.5f * kx, xr.y + 0.5f * ky);
    } else if (MODE == 3) {
        float2 s = S2[idx];
        S2[idx] = make_float2(s.x + 2.f * kx, s.y + 2.f * ky);
        Yout[idx] = make_float2(xr.x + kx, xr.y + ky);
    } else {
        float2 s = S2[idx];
        const float c = 1.f / 6.f;
        Yout[idx] = make_float2(xr.x + (s.x + kx) * c, xr.y + (s.y + ky) * c);
    }
}

// ---------------- launch ----------------
extern "C" void kernel_launch(void* const* d_in, const int* in_sizes, int n_in,
                              void* d_out, int out_size) {
    const float* x   = (const float*)d_in[0];   // [50000, 64]
    const float* att = (const float*)d_in[1];   // [1600000, 1]
    const int*   ei  = (const int*)d_in[2];     // [2, 1600000]
    const int* src = ei;
    const int* dst = ei + EE;
    float* out = (float*)d_out;

    const int T = 256;
    const int zb = (NN + T - 1) / T;
    const int eb = (EE + T - 1) / T;
    const int sb = (NN * 32 + T - 1) / T;   // 1 warp per node row

    k_zero<<<zb, T>>>();

    for (int p = 0; p < 4; p++) {
        k_hist<<<1024, T>>>(att, p);
        k_resolve<<<1, 256>>>(p);
    }

    k_edge1<<<eb, T>>>(att, src, dst);
    k_scan<<<1, 1024>>>();
    k_scatter<<<eb, T>>>(att, src, dst);

    k_stage<1><<<sb, T>>>((const float2*)x, (float2*)out);
    k_stage<2><<<sb, T>>>((const float2*)x, (float2*)out);
    k_stage<3><<<sb, T>>>((const float2*)x, (float2*)out);
    k_stage<4><<<sb, T>>>((const float2*)x, (float2*)out);
}

// round 8
// speedup vs baseline: 1.3679x; 1.0990x over previous
#include <cuda_runtime.h>
#include <cuda_fp16.h>
#include <cstdint>

// Problem constants
#define NN 50000
#define NND 50176          // NN padded to 49*1024 for uint4 deg scan
#define EE 1600000
#define K0 319999u         // floor(0.2*(E-1)) rank (ascending, 0-based)
#define K1 320000u
#define EPS 1e-16f
#define CAP 4096

// ---------------- device scratch (static, no allocation) ----------------
__device__ unsigned g_hist16[65536];
__device__ unsigned g_chunk[64];
__device__ unsigned g_binid[2];
__device__ unsigned g_cumbefore[2];
__device__ unsigned g_cand_cnt[2];
__device__ float    g_cand[2][CAP];
__device__ float    g_thr;

__device__ float    g_attsums[NN];
__device__ __align__(16) unsigned g_deg[NND];
__device__ __align__(16) unsigned g_rowstart[NN + 1];
__device__ __align__(16) unsigned g_cursor[NN];
__device__ unsigned g_bsum[49];
__device__ unsigned g_bpref[49];

__device__ int      g_srcs[EE];
__device__ float    g_w[EE];

__device__ __align__(256) float  g_Y1[NN * 64];
__device__ __align__(256) float  g_Y2[NN * 64];
__device__ __align__(256) float  g_S [NN * 64];
__device__ __align__(256) __half g_H0[NN * 64];   // fp16 gather shadow (ping)
__device__ __align__(256) __half g_H1[NN * 64];   // fp16 gather shadow (pong)

// ---------------- zero ----------------
__global__ void k_zero() {
    int i = blockIdx.x * blockDim.x + threadIdx.x;   // 65536 threads
    if (i < 65536) g_hist16[i] = 0u;
    if (i < NND)   g_deg[i] = 0u;
    if (i < NN)    g_attsums[i] = 0.f;
    if (i < 2)     g_cand_cnt[i] = 0u;
}

// ---------------- quantile: 16-bit histogram, single full pass ----------------
// att in [0,1): positive floats, uint bit pattern order-isomorphic to value.
__global__ void k_hist16(const float4* __restrict__ att4) {
    int stride = gridDim.x * blockDim.x;
    for (int i = blockIdx.x * blockDim.x + threadIdx.x; i < EE / 4; i += stride) {
        float4 v = att4[i];
        atomicAdd(&g_hist16[__float_as_uint(v.x) >> 16], 1u);
        atomicAdd(&g_hist16[__float_as_uint(v.y) >> 16], 1u);
        atomicAdd(&g_hist16[__float_as_uint(v.z) >> 16], 1u);
        atomicAdd(&g_hist16[__float_as_uint(v.w) >> 16], 1u);
    }
}

// 64 blocks: each reduces a 1024-bin chunk (uint4 coalesced) -> g_chunk
__global__ void k_coarse() {
    __shared__ unsigned red[256];
    int c = blockIdx.x, t = threadIdx.x;
    const uint4* h4 = (const uint4*)(g_hist16 + c * 1024);
    uint4 v = h4[t];
    red[t] = v.x + v.y + v.z + v.w;
    __syncthreads();
    for (int off = 128; off > 0; off >>= 1) {
        if (t < off) red[t] += red[t + off];
        __syncthreads();
    }
    if (t == 0) g_chunk[c] = red[0];
}

// 1 block: chunk prefix (64) + fine 1024-bin scan of the target chunk(s)
__global__ void k_fine() {
    __shared__ unsigned cpref[65];
    __shared__ unsigned s[1024];
    __shared__ unsigned sc, scum;
    int t = threadIdx.x;
    if (t == 0) {
        unsigned run = 0;
        for (int c = 0; c < 64; c++) { cpref[c] = run; run += g_chunk[c]; }
        cpref[64] = run;
    }
    __syncthreads();
    for (int sel = 0; sel < 2; sel++) {
        unsigned rank = sel ? K1 : K0;
        if (t < 64 && rank >= cpref[t] && rank < cpref[t + 1]) { sc = t; scum = cpref[t]; }
        __syncthreads();
        unsigned mc = sc, mcum = scum;
        unsigned c = g_hist16[mc * 1024 + t];
        s[t] = c;
        __syncthreads();
        for (int off = 1; off < 1024; off <<= 1) {
            unsigned v = (t >= off) ? s[t - off] : 0u;
            __syncthreads();
            s[t] += v;
            __syncthreads();
        }
        unsigned r = rank - mcum;
        if (r < s[t] && r >= s[t] - c) {
            g_binid[sel] = mc * 1024 + t;
            g_cumbefore[sel] = mcum + s[t] - c;
        }
        __syncthreads();
    }
}

// collect candidate values whose hi-16 bits match the target bin(s)
__global__ void k_collect(const float4* __restrict__ att4) {
    unsigned b0 = g_binid[0], b1 = g_binid[1];
    int stride = gridDim.x * blockDim.x;
    for (int i = blockIdx.x * blockDim.x + threadIdx.x; i < EE / 4; i += stride) {
        float4 v = att4[i];
        float a[4] = {v.x, v.y, v.z, v.w};
        #pragma unroll
        for (int j = 0; j < 4; j++) {
            unsigned hi = __float_as_uint(a[j]) >> 16;
            if (hi == b0) {
                unsigned p = atomicAdd(&g_cand_cnt[0], 1u);
                if (p < CAP) g_cand[0][p] = a[j];
            } else if (hi == b1) {
                unsigned p = atomicAdd(&g_cand_cnt[1], 1u);
                if (p < CAP) g_cand[1][p] = a[j];
            }
        }
    }
}

// exact order statistics via 2x 8-bit in-smem radix refinement (R6-proven)
__global__ void k_select() {
    __shared__ unsigned skey[CAP];
    __shared__ unsigned h[257];
    __shared__ unsigned sb1, srank2, sb0;
    __shared__ float vsel[2];
    int t = threadIdx.x;
    unsigned b0id = g_binid[0], b1id = g_binid[1];

    for (int sel = 0; sel < 2; sel++) {
        int bufi = (sel == 1 && b1id != b0id) ? 1 : 0;
        unsigned bin = (sel == 0) ? b0id : b1id;
        unsigned rank = ((sel == 0) ? K0 : K1) - g_cumbefore[sel];
        unsigned n = min(g_cand_cnt[bufi], (unsigned)CAP);

        for (int i = t; i < CAP; i += 1024)
            skey[i] = (i < (int)n) ? __float_as_uint(g_cand[bufi][i]) : 0xFFFFFFFFu;
        if (t < 257) h[t] = 0u;
        __syncthreads();

        for (int i = t; i < (int)n; i += 1024) atomicAdd(&h[(skey[i] >> 8) & 255u], 1u);
        __syncthreads();
        if (t == 0) { unsigned run = 0; for (int b = 0; b < 256; b++) { unsigned c = h[b]; h[b] = run; run += c; } h[256] = run; }
        __syncthreads();
        if (t < 256 && h[t] <= rank && rank < h[t + 1]) { sb1 = t; srank2 = rank - h[t]; }
        __syncthreads();
        unsigned mb1 = sb1, r2 = srank2;
        __syncthreads();
        if (t < 257) h[t] = 0u;
        __syncthreads();

        for (int i = t; i < (int)n; i += 1024) {
            unsigned k = skey[i];
            if (((k >> 8) & 255u) == mb1) atomicAdd(&h[k & 255u], 1u);
        }
        __syncthreads();
        if (t == 0) { unsigned run = 0; for (int b = 0; b < 256; b++) { unsigned c = h[b]; h[b] = run; run += c; } h[256] = run; }
        __syncthreads();
        if (t < 256 && h[t] <= r2 && r2 < h[t + 1]) sb0 = t;
        __syncthreads();

        if (t == 0) vsel[sel] = __uint_as_float((bin << 16) | (mb1 << 8) | sb0);
        __syncthreads();
    }
    if (t == 0) g_thr = vsel[0] + 0.8f * (vsel[1] - vsel[0]);
}

// ---------------- kept-edge pass: att_sums over src + degree over dst ----------------
__global__ void k_edge1(const float* __restrict__ att,
                        const int* __restrict__ src,
                        const int* __restrict__ dst) {
    int e = blockIdx.x * blockDim.x + threadIdx.x;
    if (e >= EE) return;
    float a = att[e];
    if (a > g_thr) {
        atomicAdd(&g_attsums[src[e]], a);
        atomicAdd(&g_deg[dst[e]], 1u);
    }
}

// ---------------- degree scan: 3-kernel multi-block (coalesced uint4) ----------------
__global__ void k_degpart() {    // 49 blocks x 256: block b sums deg[b*1024 .. +1024)
    __shared__ unsigned red[256];
    int b = blockIdx.x, t = threadIdx.x;
    uint4 v = ((const uint4*)g_deg)[b * 256 + t];
    red[t] = v.x + v.y + v.z + v.w;
    __syncthreads();
    for (int off = 128; off > 0; off >>= 1) {
        if (t < off) red[t] += red[t + off];
        __syncthreads();
    }
    if (t == 0) g_bsum[b] = red[0];
}

__global__ void k_degscan() {    // 1 thread: 49 values
    if (threadIdx.x == 0) {
        unsigned run = 0;
        for (int b = 0; b < 49; b++) { g_bpref[b] = run; run += g_bsum[b]; }
        g_rowstart[NN] = run;
    }
}

__global__ void k_degscatter() { // 49 blocks x 256: block-local scan + write rowstart/cursor
    __shared__ unsigned s[256];
    int b = blockIdx.x, t = threadIdx.x;
    uint4 v = ((const uint4*)g_deg)[b * 256 + t];
    unsigned mysum = v.x + v.y + v.z + v.w;
    s[t] = mysum;
    __syncthreads();
    for (int off = 1; off < 256; off <<= 1) {
        unsigned u = (t >= off) ? s[t - off] : 0u;
        __syncthreads();
        s[t] += u;
        __syncthreads();
    }
    unsigned run = g_bpref[b] + s[t] - mysum;
    int j = b * 1024 + t * 4;
    unsigned d[4] = {v.x, v.y, v.z, v.w};
    #pragma unroll
    for (int k = 0; k < 4; k++) {
        if (j + k < NN) {
            g_rowstart[j + k] = run;
            g_cursor[j + k]   = run;
            run += d[k];
        }
    }
}

// ---------------- scatter KEPT edges into dst-sorted CSR with weights ----------------
__global__ void k_scatter(const float* __restrict__ att,
                          const int* __restrict__ src,
                          const int* __restrict__ dst) {
    int e = blockIdx.x * blockDim.x + threadIdx.x;
    if (e >= EE) return;
    float a = att[e];
    if (a <= g_thr) return;
    int s = src[e];
    int d = dst[e];
    float w = a / (g_attsums[s] + EPS);
    unsigned pos = atomicAdd(&g_cursor[d], 1u);
    g_srcs[pos] = s;
    g_w[pos] = w;
}

// ---------------- x -> fp16 shadow ----------------
__global__ void k_xcvt(const float2* __restrict__ x) {
    int i = blockIdx.x * blockDim.x + threadIdx.x;
    if (i < NN * 32) {
        float2 v = x[i];
        ((__half2*)g_H0)[i] = __floats2half2_rn(v.x, v.y);
    }
}

// ---------------- fused RK4 stage (R4-proven loop shape; fp16 gather only) -------
// MODE 1: gather H0(x);  yrow=x;  S  = k;   Y1 = x+0.5k; H1 = half(Y1)
// MODE 2: gather H1(y1); yrow=Y1; S += 2k;  Y2 = x+0.5k; H0 = half(Y2)
// MODE 3: gather H0(y2); yrow=Y2; S += 2k;  Y1 = x+k;    H1 = half(Y1)
// MODE 4: gather H1(y3); yrow=Y1; out = x + (S + k)/6
template <int MODE>
__global__ void k_stage(const float2* __restrict__ x, float2* __restrict__ out) {
    int gw   = (blockIdx.x * blockDim.x + threadIdx.x) >> 5;
    int lane = threadIdx.x & 31;
    if (gw >= NN) return;

    const __half2* __restrict__ Hin =
        (MODE == 1 || MODE == 3) ? (const __half2*)g_H0 : (const __half2*)g_H1;

    unsigned e0 = g_rowstart[gw];
    unsigned e1 = g_rowstart[gw + 1];

    float ax = 0.f, ay = 0.f;
    for (unsigned e = e0; e < e1; e++) {
        int s = __ldg(&g_srcs[e]);
        float wt = __ldg(&g_w[e]);
        float2 y = __half22float2(__ldg(&Hin[s * 32 + lane]));
        ax = fmaf(wt, y.x, ax);
        ay = fmaf(wt, y.y, ay);
    }

    int idx = gw * 32 + lane;
    const float2* Yin = (MODE == 1) ? x
                      : (MODE == 2) ? (const float2*)g_Y1
                      : (MODE == 3) ? (const float2*)g_Y2
                                    : (const float2*)g_Y1;
    float2 yr = Yin[idx];
    float kx = ax - yr.x;
    float ky = ay - yr.y;
    float2 xr = (MODE == 1) ? yr : x[idx];
    float2* S2 = (float2*)g_S;

    if (MODE == 1) {
        S2[idx] = make_float2(kx, ky);
        float nx = xr.x + 0.5f * kx, ny = xr.y + 0.5f * ky;
        ((float2*)g_Y1)[idx] = make_float2(nx, ny);
        ((__half2*)g_H1)[idx] = __floats2half2_rn(nx, ny);
    } else if (MODE == 2) {
        float2 s = S2[idx];
        S2[idx] = make_float2(s.x + 2.f * kx, s.y + 2.f * ky);
        float nx = xr.x + 0.5f * kx, ny = xr.y + 0.5f * ky;
        ((float2*)g_Y2)[idx] = make_float2(nx, ny);
        ((__half2*)g_H0)[idx] = __floats2half2_rn(nx, ny);
    } else if (MODE == 3) {
        float2 s = S2[idx];
        S2[idx] = make_float2(s.x + 2.f * kx, s.y + 2.f * ky);
        float nx = xr.x + kx, ny = xr.y + ky;
        ((float2*)g_Y1)[idx] = make_float2(nx, ny);
        ((__half2*)g_H1)[idx] = __floats2half2_rn(nx, ny);
    } else {
        float2 s = S2[idx];
        const float c = 1.f / 6.f;
        out[idx] = make_float2(xr.x + (s.x + kx) * c, xr.y + (s.y + ky) * c);
    }
}

// ---------------- launch ----------------
extern "C" void kernel_launch(void* const* d_in, const int* in_sizes, int n_in,
                              void* d_out, int out_size) {
    const float* x   = (const float*)d_in[0];   // [50000, 64]
    const float* att = (const float*)d_in[1];   // [1600000, 1]
    const int*   ei  = (const int*)d_in[2];     // [2, 1600000]
    const int* src = ei;
    const int* dst = ei + EE;
    float* out = (float*)d_out;

    const int T = 256;
    const int eb = (EE + T - 1) / T;            // 6250
    const int sb = (NN * 32 + T - 1) / T;       // 6250 (warp per row)

    k_zero<<<256, T>>>();
    k_hist16<<<1024, T>>>((const float4*)att);
    k_coarse<<<64, T>>>();
    k_fine<<<1, 1024>>>();
    k_collect<<<1024, T>>>((const float4*)att);
    k_select<<<1, 1024>>>();
    k_edge1<<<eb, T>>>(att, src, dst);
    k_degpart<<<49, T>>>();
    k_degscan<<<1, 32>>>();
    k_degscatter<<<49, T>>>();
    k_scatter<<<eb, T>>>(att, src, dst);
    k_xcvt<<<sb, T>>>((const float2*)x);

    k_stage<1><<<sb, T>>>((const float2*)x, (float2*)out);
    k_stage<2><<<sb, T>>>((const float2*)x, (float2*)out);
    k_stage<3><<<sb, T>>>((const float2*)x, (float2*)out);
    k_stage<4><<<sb, T>>>((const float2*)x, (float2*)out);
}

// round 10
// speedup vs baseline: 1.4206x; 1.0385x over previous
#include <cuda_runtime.h>
#include <cuda_fp16.h>
#include <cstdint>

// Problem constants
#define NN 50000
#define NND 50176          // NN padded to 49*1024 for uint4 deg scan
#define EE 1600000
#define K0 319999u         // floor(0.2*(E-1)) rank (ascending, 0-based)
#define K1 320000u
#define EPS 1e-16f
#define CAP 4096

// ---------------- device scratch (static, no allocation) ----------------
__device__ unsigned g_hist16[65536];
__device__ unsigned g_chunk[64];
__device__ unsigned g_binid[2];
__device__ unsigned g_cumbefore[2];
__device__ unsigned g_cand_cnt[2];
__device__ float    g_cand[2][CAP];
__device__ float    g_thr;

__device__ float    g_attsums[NN];
__device__ __align__(16) unsigned g_deg[NND];
__device__ __align__(16) unsigned g_rowstart[NN + 1];
__device__ __align__(16) unsigned g_cursor[NN];
__device__ unsigned g_bsum[49];
__device__ unsigned g_bpref[49];

__device__ __align__(16) int2 g_edges[EE];        // (src, bitcast(w)) kept edges, dst-sorted

__device__ __align__(256) float  g_Y1[NN * 64];
__device__ __align__(256) float  g_Y2[NN * 64];
__device__ __align__(256) float  g_S [NN * 64];
__device__ __align__(256) __half g_H0[NN * 64];   // fp16 gather shadow (ping)
__device__ __align__(256) __half g_H1[NN * 64];   // fp16 gather shadow (pong)

// ---------------- zero ----------------
__global__ void k_zero() {
    int i = blockIdx.x * blockDim.x + threadIdx.x;   // 65536 threads
    if (i < 65536) g_hist16[i] = 0u;
    if (i < NND)   g_deg[i] = 0u;
    if (i < NN)    g_attsums[i] = 0.f;
    if (i < 2)     g_cand_cnt[i] = 0u;
}

// ---------------- quantile: 16-bit histogram, single full pass ----------------
// att in [0,1): positive floats, uint bit pattern order-isomorphic to value.
__global__ void k_hist16(const float4* __restrict__ att4) {
    int stride = gridDim.x * blockDim.x;
    for (int i = blockIdx.x * blockDim.x + threadIdx.x; i < EE / 4; i += stride) {
        float4 v = att4[i];
        atomicAdd(&g_hist16[__float_as_uint(v.x) >> 16], 1u);
        atomicAdd(&g_hist16[__float_as_uint(v.y) >> 16], 1u);
        atomicAdd(&g_hist16[__float_as_uint(v.z) >> 16], 1u);
        atomicAdd(&g_hist16[__float_as_uint(v.w) >> 16], 1u);
    }
}

// 64 blocks: each reduces a 1024-bin chunk (uint4 coalesced) -> g_chunk
__global__ void k_coarse() {
    __shared__ unsigned red[256];
    int c = blockIdx.x, t = threadIdx.x;
    const uint4* h4 = (const uint4*)(g_hist16 + c * 1024);
    uint4 v = h4[t];
    red[t] = v.x + v.y + v.z + v.w;
    __syncthreads();
    for (int off = 128; off > 0; off >>= 1) {
        if (t < off) red[t] += red[t + off];
        __syncthreads();
    }
    if (t == 0) g_chunk[c] = red[0];
}

// 1 block (1024 thr): parallel chunk scan (64) + fine 1024-bin scan of target chunk(s)
__global__ void k_fine() {
    __shared__ unsigned cs[64];
    __shared__ unsigned s[1024];
    __shared__ unsigned sc, scum;
    int t = threadIdx.x;
    unsigned cv = (t < 64) ? g_chunk[t] : 0u;
    if (t < 64) cs[t] = cv;
    __syncthreads();
    for (int off = 1; off < 64; off <<= 1) {
        unsigned v = (t < 64 && t >= off) ? cs[t - off] : 0u;
        __syncthreads();
        if (t < 64) cs[t] += v;
        __syncthreads();
    }
    // cs = inclusive prefix of chunk sums
    for (int sel = 0; sel < 2; sel++) {
        unsigned rank = sel ? K1 : K0;
        if (t < 64 && rank < cs[t] && rank >= cs[t] - cv) { sc = t; scum = cs[t] - cv; }
        __syncthreads();
        unsigned mc = sc, mcum = scum;
        unsigned c = g_hist16[mc * 1024 + t];
        s[t] = c;
        __syncthreads();
        for (int off = 1; off < 1024; off <<= 1) {
            unsigned v = (t >= off) ? s[t - off] : 0u;
            __syncthreads();
            s[t] += v;
            __syncthreads();
        }
        unsigned r = rank - mcum;
        if (r < s[t] && r >= s[t] - c) {
            g_binid[sel] = mc * 1024 + t;
            g_cumbefore[sel] = mcum + s[t] - c;
        }
        __syncthreads();
    }
}

// collect candidate values whose hi-16 bits match the target bin(s)
__global__ void k_collect(const float4* __restrict__ att4) {
    unsigned b0 = g_binid[0], b1 = g_binid[1];
    int stride = gridDim.x * blockDim.x;
    for (int i = blockIdx.x * blockDim.x + threadIdx.x; i < EE / 4; i += stride) {
        float4 v = att4[i];
        float a[4] = {v.x, v.y, v.z, v.w};
        #pragma unroll
        for (int j = 0; j < 4; j++) {
            unsigned hi = __float_as_uint(a[j]) >> 16;
            if (hi == b0) {
                unsigned p = atomicAdd(&g_cand_cnt[0], 1u);
                if (p < CAP) g_cand[0][p] = a[j];
            } else if (hi == b1) {
                unsigned p = atomicAdd(&g_cand_cnt[1], 1u);
                if (p < CAP) g_cand[1][p] = a[j];
            }
        }
    }
}

// exact order statistics via 2x 8-bit radix refine; all scans parallel (256 thr)
__global__ void k_select() {
    __shared__ unsigned cnt[256];
    __shared__ unsigned inc[256];
    __shared__ unsigned sb1, srank2, sb0;
    __shared__ float vsel[2];
    int t = threadIdx.x;   // 256 threads
    unsigned b0id = g_binid[0], b1id = g_binid[1];

    for (int sel = 0; sel < 2; sel++) {
        int bufi = (sel == 1 && b1id != b0id) ? 1 : 0;
        unsigned bin = (sel == 0) ? b0id : b1id;
        unsigned rank = ((sel == 0) ? K0 : K1) - g_cumbefore[sel];
        unsigned n = min(g_cand_cnt[bufi], (unsigned)CAP);

        // ---- pass on byte1 (bits 15:8) ----
        cnt[t] = 0u;
        __syncthreads();
        for (int i = t; i < (int)n; i += 256)
            atomicAdd(&cnt[(__float_as_uint(g_cand[bufi][i]) >> 8) & 255u], 1u);
        __syncthreads();
        unsigned c = cnt[t];
        inc[t] = c;
        __syncthreads();
        for (int off = 1; off < 256; off <<= 1) {
            unsigned v = (t >= off) ? inc[t - off] : 0u;
            __syncthreads();
            inc[t] += v;
            __syncthreads();
        }
        if (rank < inc[t] && rank >= inc[t] - c) { sb1 = t; srank2 = rank - (inc[t] - c); }
        __syncthreads();
        unsigned mb1 = sb1, r2 = srank2;
        __syncthreads();

        // ---- pass on byte0 (bits 7:0) among matching byte1 ----
        cnt[t] = 0u;
        __syncthreads();
        for (int i = t; i < (int)n; i += 256) {
            unsigned k = __float_as_uint(g_cand[bufi][i]);
            if (((k >> 8) & 255u) == mb1) atomicAdd(&cnt[k & 255u], 1u);
        }
        __syncthreads();
        c = cnt[t];
        inc[t] = c;
        __syncthreads();
        for (int off = 1; off < 256; off <<= 1) {
            unsigned v = (t >= off) ? inc[t - off] : 0u;
            __syncthreads();
            inc[t] += v;
            __syncthreads();
        }
        if (r2 < inc[t] && r2 >= inc[t] - c) sb0 = t;
        __syncthreads();

        if (t == 0) vsel[sel] = __uint_as_float((bin << 16) | (mb1 << 8) | sb0);
        __syncthreads();
    }
    if (t == 0) g_thr = vsel[0] + 0.8f * (vsel[1] - vsel[0]);
}

// ---------------- kept-edge pass: att_sums over src + degree over dst ----------------
__global__ void k_edge1(const float* __restrict__ att,
                        const int* __restrict__ src,
                        const int* __restrict__ dst) {
    int e = blockIdx.x * blockDim.x + threadIdx.x;
    if (e >= EE) return;
    float a = att[e];
    if (a > g_thr) {
        atomicAdd(&g_attsums[src[e]], a);
        atomicAdd(&g_deg[dst[e]], 1u);
    }
}

// ---------------- degree scan: 3-kernel multi-block (coalesced uint4) ----------------
__global__ void k_degpart() {    // 49 blocks x 256
    __shared__ unsigned red[256];
    int b = blockIdx.x, t = threadIdx.x;
    uint4 v = ((const uint4*)g_deg)[b * 256 + t];
    red[t] = v.x + v.y + v.z + v.w;
    __syncthreads();
    for (int off = 128; off > 0; off >>= 1) {
        if (t < off) red[t] += red[t + off];
        __syncthreads();
    }
    if (t == 0) g_bsum[b] = red[0];
}

__global__ void k_degscan() {    // 1 block x 64: parallel scan over 49
    __shared__ unsigned s[64];
    int t = threadIdx.x;
    unsigned v = (t < 49) ? g_bsum[t] : 0u;
    s[t] = v;
    __syncthreads();
    for (int off = 1; off < 64; off <<= 1) {
        unsigned u = (t >= off) ? s[t - off] : 0u;
        __syncthreads();
        s[t] += u;
        __syncthreads();
    }
    if (t < 49) g_bpref[t] = s[t] - v;
    if (t == 48) g_rowstart[NN] = s[48];
}

__global__ void k_degscatter() { // 49 blocks x 256
    __shared__ unsigned s[256];
    int b = blockIdx.x, t = threadIdx.x;
    uint4 v = ((const uint4*)g_deg)[b * 256 + t];
    unsigned mysum = v.x + v.y + v.z + v.w;
    s[t] = mysum;
    __syncthreads();
    for (int off = 1; off < 256; off <<= 1) {
        unsigned u = (t >= off) ? s[t - off] : 0u;
        __syncthreads();
        s[t] += u;
        __syncthreads();
    }
    unsigned run = g_bpref[b] + s[t] - mysum;
    int j = b * 1024 + t * 4;
    unsigned d[4] = {v.x, v.y, v.z, v.w};
    #pragma unroll
    for (int k = 0; k < 4; k++) {
        if (j + k < NN) {
            g_rowstart[j + k] = run;
            g_cursor[j + k]   = run;
            run += d[k];
        }
    }
}

// ---------------- scatter KEPT edges into dst-sorted CSR with weights ----------------
__global__ void k_scatter(const float* __restrict__ att,
                          const int* __restrict__ src,
                          const int* __restrict__ dst) {
    int e = blockIdx.x * blockDim.x + threadIdx.x;
    if (e >= EE) return;
    float a = att[e];
    if (a <= g_thr) return;
    int s = src[e];
    int d = dst[e];
    float w = a / (g_attsums[s] + EPS);
    unsigned pos = atomicAdd(&g_cursor[d], 1u);
    g_edges[pos] = make_int2(s, __float_as_int(w));
}

// ---------------- x -> fp16 shadow ----------------
__global__ void k_xcvt(const float2* __restrict__ x) {
    int i = blockIdx.x * blockDim.x + threadIdx.x;
    if (i < NN * 32) {
        float2 v = x[i];
        ((__half2*)g_H0)[i] = __floats2half2_rn(v.x, v.y);
    }
}

// ---------------- fused RK4 stage: batched-MLP gather loop -------------------------
// MODE 1: gather H0(x);  yrow=x;  S  = k;   Y1 = x+0.5k; H1 = half(Y1)
// MODE 2: gather H1(y1); yrow=Y1; S += 2k;  Y2 = x+0.5k; H0 = half(Y2)
// MODE 3: gather H0(y2); yrow=Y2; S += 2k;  Y1 = x+k;    H1 = half(Y1)
// MODE 4: gather H1(y3); yrow=Y1; out = x + (S + k)/6
template <int MODE>
__global__ void k_stage(const float2* __restrict__ x, float2* __restrict__ out) {
    int gw   = (blockIdx.x * blockDim.x + threadIdx.x) >> 5;
    int lane = threadIdx.x & 31;
    if (gw >= NN) return;

    const __half2* __restrict__ Hin =
        (MODE == 1 || MODE == 3) ? (const __half2*)g_H0 : (const __half2*)g_H1;

    unsigned e0 = g_rowstart[gw];
    unsigned e1 = g_rowstart[gw + 1];

    float ax = 0.f, ay = 0.f, bx = 0.f, by = 0.f;
    unsigned e = e0;
    // batch 8 edges: 8 edge loads in flight, then 8 independent gathers in flight
    for (; e + 8 <= e1; e += 8) {
        int2 E[8];
        #pragma unroll
        for (int j = 0; j < 8; j++) E[j] = __ldg(&g_edges[e + j]);
        __half2 H[8];
        #pragma unroll
        for (int j = 0; j < 8; j++) H[j] = __ldg(&Hin[E[j].x * 32 + lane]);
        #pragma unroll
        for (int j = 0; j < 8; j++) {
            float2 y = __half22float2(H[j]);
            float w = __int_as_float(E[j].y);
            if (j & 1) { bx = fmaf(w, y.x, bx); by = fmaf(w, y.y, by); }
            else       { ax = fmaf(w, y.x, ax); ay = fmaf(w, y.y, ay); }
        }
    }
    for (; e < e1; e++) {
        int2 p = __ldg(&g_edges[e]);
        float2 y = __half22float2(__ldg(&Hin[p.x * 32 + lane]));
        float w = __int_as_float(p.y);
        ax = fmaf(w, y.x, ax); ay = fmaf(w, y.y, ay);
    }
    ax += bx; ay += by;

    int idx = gw * 32 + lane;
    const float2* Yin = (MODE == 1) ? x
                      : (MODE == 2) ? (const float2*)g_Y1
                      : (MODE == 3) ? (const float2*)g_Y2
                                    : (const float2*)g_Y1;
    float2 yr = Yin[idx];
    float kx = ax - yr.x;
    float ky = ay - yr.y;
    float2 xr = (MODE == 1) ? yr : x[idx];
    float2* S2 = (float2*)g_S;

    if (MODE == 1) {
        S2[idx] = make_float2(kx, ky);
        float nx = xr.x + 0.5f * kx, ny = xr.y + 0.5f * ky;
        ((float2*)g_Y1)[idx] = make_float2(nx, ny);
        ((__half2*)g_H1)[idx] = __floats2half2_rn(nx, ny);
    } else if (MODE == 2) {
        float2 s = S2[idx];
        S2[idx] = make_float2(s.x + 2.f * kx, s.y + 2.f * ky);
        float nx = xr.x + 0.5f * kx, ny = xr.y + 0.5f * ky;
        ((float2*)g_Y2)[idx] = make_float2(nx, ny);
        ((__half2*)g_H0)[idx] = __floats2half2_rn(nx, ny);
    } else if (MODE == 3) {
        float2 s = S2[idx];
        S2[idx] = make_float2(s.x + 2.f * kx, s.y + 2.f * ky);
        float nx = xr.x + kx, ny = xr.y + ky;
        ((float2*)g_Y1)[idx] = make_float2(nx, ny);
        ((__half2*)g_H1)[idx] = __floats2half2_rn(nx, ny);
    } else {
        float2 s = S2[idx];
        const float c = 1.f / 6.f;
        out[idx] = make_float2(xr.x + (s.x + kx) * c, xr.y + (s.y + ky) * c);
    }
}

// ---------------- launch ----------------
extern "C" void kernel_launch(void* const* d_in, const int* in_sizes, int n_in,
                              void* d_out, int out_size) {
    const float* x   = (const float*)d_in[0];   // [50000, 64]
    const float* att = (const float*)d_in[1];   // [1600000, 1]
    const int*   ei  = (const int*)d_in[2];     // [2, 1600000]
    const int* src = ei;
    const int* dst = ei + EE;
    float* out = (float*)d_out;

    const int T = 256;
    const int eb = (EE + T - 1) / T;            // 6250
    const int sb = (NN * 32 + T - 1) / T;       // 6250 (warp per row)

    k_zero<<<256, T>>>();
    k_hist16<<<1024, T>>>((const float4*)att);
    k_coarse<<<64, T>>>();
    k_fine<<<1, 1024>>>();
    k_collect<<<1024, T>>>((const float4*)att);
    k_select<<<1, 256>>>();
    k_edge1<<<eb, T>>>(att, src, dst);
    k_degpart<<<49, T>>>();
    k_degscan<<<1, 64>>>();
    k_degscatter<<<49, T>>>();
    k_scatter<<<eb, T>>>(att, src, dst);
    k_xcvt<<<sb, T>>>((const float2*)x);

    k_stage<1><<<sb, T>>>((const float2*)x, (float2*)out);
    k_stage<2><<<sb, T>>>((const float2*)x, (float2*)out);
    k_stage<3><<<sb, T>>>((const float2*)x, (float2*)out);
    k_stage<4><<<sb, T>>>((const float2*)x, (float2*)out);
}

// round 11
// speedup vs baseline: 1.4221x; 1.0011x over previous
#include <cuda_runtime.h>
#include <cuda_fp16.h>
#include <cstdint>

// Problem constants
#define NN 50000
#define NND 50176          // NN padded to 49*1024 for uint4 deg scan
#define EE 1600000
#define K0 319999u         // floor(0.2*(E-1)) rank (ascending, 0-based)
#define K1 320000u
#define EPS 1e-16f
#define CAP 8192

// ---------------- device scratch (static, no allocation) ----------------
__device__ unsigned g_hist16[65536];
__device__ unsigned g_binid[2];
__device__ unsigned g_cumbefore[2];
__device__ unsigned g_cand_cnt[2];
__device__ float    g_cand[2][CAP];
__device__ int      g_cidx[2][CAP];
__device__ float    g_thr;

__device__ float    g_attsums[NN];
__device__ __align__(16) unsigned g_deg[NND];
__device__ __align__(16) unsigned g_rowstart[NN + 1];
__device__ __align__(16) unsigned g_cursor[NN];

__device__ __align__(16) int2 g_edges[EE];        // (src, bitcast(w)) kept edges, dst-sorted

__device__ __align__(256) float  g_Y1[NN * 64];
__device__ __align__(256) float  g_Y2[NN * 64];
__device__ __align__(256) float  g_S [NN * 64];
__device__ __align__(256) __half g_H0[NN * 64];   // fp16 gather shadow (ping)
__device__ __align__(256) __half g_H1[NN * 64];   // fp16 gather shadow (pong)

// ---------------- 1: zero ----------------
__global__ void k_zero() {
    int i = blockIdx.x * blockDim.x + threadIdx.x;   // 65536 threads
    if (i < 65536) g_hist16[i] = 0u;
    if (i < NND)   g_deg[i] = 0u;
    if (i < NN)    g_attsums[i] = 0.f;
    if (i < 2)     g_cand_cnt[i] = 0u;
}

// ---------------- 2: quantile 16-bit histogram, single full pass ----------------
// att in [0,1): positive floats, uint bit pattern order-isomorphic to value.
__global__ void k_hist16(const float4* __restrict__ att4) {
    int stride = gridDim.x * blockDim.x;
    for (int i = blockIdx.x * blockDim.x + threadIdx.x; i < EE / 4; i += stride) {
        float4 v = att4[i];
        atomicAdd(&g_hist16[__float_as_uint(v.x) >> 16], 1u);
        atomicAdd(&g_hist16[__float_as_uint(v.y) >> 16], 1u);
        atomicAdd(&g_hist16[__float_as_uint(v.z) >> 16], 1u);
        atomicAdd(&g_hist16[__float_as_uint(v.w) >> 16], 1u);
    }
}

// ---------------- 3: one-block fused coarse+fine bin search ----------------
// 1024 threads. Coalesced uint4 read of 65536 bins; chunk sums via warp reduce;
// chunk scan; fine scan of the target chunk(s).
__global__ void k_qscan() {
    __shared__ unsigned chs[64];
    __shared__ unsigned s[1024];
    __shared__ unsigned sc, scum;
    int t = threadIdx.x;
    int w = t >> 5, lane = t & 31;

    // warp w covers chunks 2w and 2w+1; each chunk = 256 uint4
    #pragma unroll
    for (int h = 0; h < 2; h++) {
        int c = w * 2 + h;
        unsigned acc = 0;
        #pragma unroll
        for (int k = 0; k < 8; k++) {
            uint4 v = ((const uint4*)g_hist16)[c * 256 + lane + 32 * k];
            acc += v.x + v.y + v.z + v.w;
        }
        #pragma unroll
        for (int off = 16; off > 0; off >>= 1)
            acc += __shfl_down_sync(0xFFFFFFFFu, acc, off);
        if (lane == 0) chs[c] = acc;
    }
    __syncthreads();
    // inclusive scan of 64 chunk sums (threads 0..63)
    unsigned cv = (t < 64) ? chs[t] : 0u;
    if (t < 64) s[t] = cv;
    __syncthreads();
    for (int off = 1; off < 64; off <<= 1) {
        unsigned v = (t < 64 && t >= off) ? s[t - off] : 0u;
        __syncthreads();
        if (t < 64) s[t] += v;
        __syncthreads();
    }
    __shared__ unsigned cinc[64];
    if (t < 64) cinc[t] = s[t];
    __syncthreads();

    for (int sel = 0; sel < 2; sel++) {
        unsigned rank = sel ? K1 : K0;
        if (t < 64 && rank < cinc[t] && rank >= cinc[t] - chs[t]) { sc = t; scum = cinc[t] - chs[t]; }
        __syncthreads();
        unsigned mc = sc, mcum = scum;
        unsigned c = g_hist16[mc * 1024 + t];
        s[t] = c;
        __syncthreads();
        for (int off = 1; off < 1024; off <<= 1) {
            unsigned v = (t >= off) ? s[t - off] : 0u;
            __syncthreads();
            s[t] += v;
            __syncthreads();
        }
        unsigned r = rank - mcum;
        if (r < s[t] && r >= s[t] - c) {
            g_binid[sel] = mc * 1024 + t;
            g_cumbefore[sel] = mcum + s[t] - c;
        }
        __syncthreads();
    }
}

// ---------------- 4: fused collect + tentative edge stats ----------------
// tentative keep: bits(a) > FLOOR where FLOOR = binid0<<16 (lowest possible v0).
// Extras (FLOOR < a <= thr) are all candidates and get fixed up in k_select.
__global__ void k_colledge(const float4* __restrict__ att4,
                           const int* __restrict__ src,
                           const int* __restrict__ dst) {
    unsigned b0 = g_binid[0], b1 = g_binid[1];
    unsigned FLOOR = b0 << 16;
    int stride = gridDim.x * blockDim.x;
    for (int i = blockIdx.x * blockDim.x + threadIdx.x; i < EE / 4; i += stride) {
        float4 v = att4[i];
        float a[4] = {v.x, v.y, v.z, v.w};
        #pragma unroll
        for (int j = 0; j < 4; j++) {
            unsigned bits = __float_as_uint(a[j]);
            unsigned hi = bits >> 16;
            int e = 4 * i + j;
            if (bits > FLOOR) {
                atomicAdd(&g_attsums[src[e]], a[j]);
                atomicAdd(&g_deg[dst[e]], 1u);
            }
            if (hi == b0) {
                unsigned p = atomicAdd(&g_cand_cnt[0], 1u);
                if (p < CAP) { g_cand[0][p] = a[j]; g_cidx[0][p] = e; }
            } else if (hi == b1) {
                unsigned p = atomicAdd(&g_cand_cnt[1], 1u);
                if (p < CAP) { g_cand[1][p] = a[j]; g_cidx[1][p] = e; }
            }
        }
    }
}

// ---------------- 5: exact order statistics + threshold + edge fixup ----------------
__global__ void k_select(const int* __restrict__ src, const int* __restrict__ dst) {
    __shared__ unsigned cnt[256];
    __shared__ unsigned inc[256];
    __shared__ unsigned sb1, srank2, sb0;
    __shared__ float vsel[2];
    int t = threadIdx.x;   // 256 threads
    unsigned b0id = g_binid[0], b1id = g_binid[1];

    for (int sel = 0; sel < 2; sel++) {
        int bufi = (sel == 1 && b1id != b0id) ? 1 : 0;
        unsigned bin = (sel == 0) ? b0id : b1id;
        unsigned rank = ((sel == 0) ? K0 : K1) - g_cumbefore[sel];
        unsigned n = min(g_cand_cnt[bufi], (unsigned)CAP);

        // ---- pass on byte1 (bits 15:8) ----
        cnt[t] = 0u;
        __syncthreads();
        for (int i = t; i < (int)n; i += 256)
            atomicAdd(&cnt[(__float_as_uint(g_cand[bufi][i]) >> 8) & 255u], 1u);
        __syncthreads();
        unsigned c = cnt[t];
        inc[t] = c;
        __syncthreads();
        for (int off = 1; off < 256; off <<= 1) {
            unsigned v = (t >= off) ? inc[t - off] : 0u;
            __syncthreads();
            inc[t] += v;
            __syncthreads();
        }
        if (rank < inc[t] && rank >= inc[t] - c) { sb1 = t; srank2 = rank - (inc[t] - c); }
        __syncthreads();
        unsigned mb1 = sb1, r2 = srank2;
        __syncthreads();

        // ---- pass on byte0 (bits 7:0) among matching byte1 ----
        cnt[t] = 0u;
        __syncthreads();
        for (int i = t; i < (int)n; i += 256) {
            unsigned k = __float_as_uint(g_cand[bufi][i]);
            if (((k >> 8) & 255u) == mb1) atomicAdd(&cnt[k & 255u], 1u);
        }
        __syncthreads();
        c = cnt[t];
        inc[t] = c;
        __syncthreads();
        for (int off = 1; off < 256; off <<= 1) {
            unsigned v = (t >= off) ? inc[t - off] : 0u;
            __syncthreads();
            inc[t] += v;
            __syncthreads();
        }
        if (r2 < inc[t] && r2 >= inc[t] - c) sb0 = t;
        __syncthreads();

        if (t == 0) vsel[sel] = __uint_as_float((bin << 16) | (mb1 << 8) | sb0);
        __syncthreads();
    }
    __shared__ float sthr;
    if (t == 0) { sthr = vsel[0] + 0.8f * (vsel[1] - vsel[0]); g_thr = sthr; }
    __syncthreads();
    float thr = sthr;
    unsigned FLOOR = b0id << 16;

    // ---- fixup: remove tentatively-kept candidates with a <= thr ----
    int nbuf = (b1id != b0id) ? 2 : 1;
    for (int b = 0; b < nbuf; b++) {
        unsigned n = min(g_cand_cnt[b], (unsigned)CAP);
        for (int i = t; i < (int)n; i += 256) {
            float a = g_cand[b][i];
            unsigned bits = __float_as_uint(a);
            if (bits > FLOOR && a <= thr) {
                int e = g_cidx[b][i];
                atomicAdd(&g_attsums[src[e]], -a);
                atomicAdd(&g_deg[dst[e]], 0xFFFFFFFFu);   // -1
            }
        }
    }
}

// ---------------- 6: fused degree CSR build (49 blocks x 256) ----------------
__global__ void k_degcsr() {
    __shared__ unsigned red[256];
    __shared__ unsigned s[256];
    __shared__ unsigned base;
    int b = blockIdx.x, t = threadIdx.x;

    // sum of all chunks before b
    unsigned acc = 0;
    for (int c = 0; c < b; c++) {
        uint4 v = ((const uint4*)g_deg)[c * 256 + t];
        acc += v.x + v.y + v.z + v.w;
    }
    red[t] = acc;
    __syncthreads();
    for (int off = 128; off > 0; off >>= 1) {
        if (t < off) red[t] += red[t + off];
        __syncthreads();
    }
    if (t == 0) base = red[0];
    __syncthreads();

    // own chunk scan
    uint4 v = ((const uint4*)g_deg)[b * 256 + t];
    unsigned mysum = v.x + v.y + v.z + v.w;
    s[t] = mysum;
    __syncthreads();
    for (int off = 1; off < 256; off <<= 1) {
        unsigned u = (t >= off) ? s[t - off] : 0u;
        __syncthreads();
        s[t] += u;
        __syncthreads();
    }
    unsigned run = base + s[t] - mysum;
    int j = b * 1024 + t * 4;
    unsigned d[4] = {v.x, v.y, v.z, v.w};
    #pragma unroll
    for (int k = 0; k < 4; k++) {
        if (j + k < NN) {
            g_rowstart[j + k] = run;
            g_cursor[j + k]   = run;
            run += d[k];
        }
    }
    if (b == 48 && t == 255) g_rowstart[NN] = base + s[255];
}

// ---------------- 7: fused scatter + x->fp16 convert (EE == NN*32) ----------------
__global__ void k_scatterx(const float* __restrict__ att,
                           const int* __restrict__ src,
                           const int* __restrict__ dst,
                           const float2* __restrict__ x) {
    int i = blockIdx.x * blockDim.x + threadIdx.x;
    if (i >= EE) return;
    // xcvt part (i indexes NN*32 float2 = 1.6M)
    float2 v = x[i];
    ((__half2*)g_H0)[i] = __floats2half2_rn(v.x, v.y);
    // scatter part
    float a = att[i];
    if (a > g_thr) {
        int s = src[i];
        int d = dst[i];
        float w = a / (g_attsums[s] + EPS);
        unsigned pos = atomicAdd(&g_cursor[d], 1u);
        g_edges[pos] = make_int2(s, __float_as_int(w));
    }
}

// ---------------- 8-11: fused RK4 stage (R10-proven) -------------------------
// MODE 1: gather H0(x);  yrow=x;  S  = k;   Y1 = x+0.5k; H1 = half(Y1)
// MODE 2: gather H1(y1); yrow=Y1; S += 2k;  Y2 = x+0.5k; H0 = half(Y2)
// MODE 3: gather H0(y2); yrow=Y2; S += 2k;  Y1 = x+k;    H1 = half(Y1)
// MODE 4: gather H1(y3); yrow=Y1; out = x + (S + k)/6
template <int MODE>
__global__ void k_stage(const float2* __restrict__ x, float2* __restrict__ out) {
    int gw   = (blockIdx.x * blockDim.x + threadIdx.x) >> 5;
    int lane = threadIdx.x & 31;
    if (gw >= NN) return;

    const __half2* __restrict__ Hin =
        (MODE == 1 || MODE == 3) ? (const __half2*)g_H0 : (const __half2*)g_H1;

    unsigned e0 = g_rowstart[gw];
    unsigned e1 = g_rowstart[gw + 1];

    float ax = 0.f, ay = 0.f, bx = 0.f, by = 0.f;
    unsigned e = e0;
    for (; e + 8 <= e1; e += 8) {
        int2 E[8];
        #pragma unroll
        for (int j = 0; j < 8; j++) E[j] = __ldg(&g_edges[e + j]);
        __half2 H[8];
        #pragma unroll
        for (int j = 0; j < 8; j++) H[j] = __ldg(&Hin[E[j].x * 32 + lane]);
        #pragma unroll
        for (int j = 0; j < 8; j++) {
            float2 y = __half22float2(H[j]);
            float w = __int_as_float(E[j].y);
            if (j & 1) { bx = fmaf(w, y.x, bx); by = fmaf(w, y.y, by); }
            else       { ax = fmaf(w, y.x, ax); ay = fmaf(w, y.y, ay); }
        }
    }
    for (; e < e1; e++) {
        int2 p = __ldg(&g_edges[e]);
        float2 y = __half22float2(__ldg(&Hin[p.x * 32 + lane]));
        float w = __int_as_float(p.y);
        ax = fmaf(w, y.x, ax); ay = fmaf(w, y.y, ay);
    }
    ax += bx; ay += by;

    int idx = gw * 32 + lane;
    const float2* Yin = (MODE == 1) ? x
                      : (MODE == 2) ? (const float2*)g_Y1
                      : (MODE == 3) ? (const float2*)g_Y2
                                    : (const float2*)g_Y1;
    float2 yr = Yin[idx];
    float kx = ax - yr.x;
    float ky = ay - yr.y;
    float2 xr = (MODE == 1) ? yr : x[idx];
    float2* S2 = (float2*)g_S;

    if (MODE == 1) {
        S2[idx] = make_float2(kx, ky);
        float nx = xr.x + 0.5f * kx, ny = xr.y + 0.5f * ky;
        ((float2*)g_Y1)[idx] = make_float2(nx, ny);
        ((__half2*)g_H1)[idx] = __floats2half2_rn(nx, ny);
    } else if (MODE == 2) {
        float2 s = S2[idx];
        S2[idx] = make_float2(s.x + 2.f * kx, s.y + 2.f * ky);
        float nx = xr.x + 0.5f * kx, ny = xr.y + 0.5f * ky;
        ((float2*)g_Y2)[idx] = make_float2(nx, ny);
        ((__half2*)g_H0)[idx] = __floats2half2_rn(nx, ny);
    } else if (MODE == 3) {
        float2 s = S2[idx];
        S2[idx] = make_float2(s.x + 2.f * kx, s.y + 2.f * ky);
        float nx = xr.x + kx, ny = xr.y + ky;
        ((float2*)g_Y1)[idx] = make_float2(nx, ny);
        ((__half2*)g_H1)[idx] = __floats2half2_rn(nx, ny);
    } else {
        float2 s = S2[idx];
        const float c = 1.f / 6.f;
        out[idx] = make_float2(xr.x + (s.x + kx) * c, xr.y + (s.y + ky) * c);
    }
}

// ---------------- launch ----------------
extern "C" void kernel_launch(void* const* d_in, const int* in_sizes, int n_in,
                              void* d_out, int out_size) {
    const float* x   = (const float*)d_in[0];   // [50000, 64]
    const float* att = (const float*)d_in[1];   // [1600000, 1]
    const int*   ei  = (const int*)d_in[2];     // [2, 1600000]
    const int* src = ei;
    const int* dst = ei + EE;
    float* out = (float*)d_out;

    const int T = 256;
    const int eb = (EE + T - 1) / T;            // 6250
    const int sb = (NN * 32 + T - 1) / T;       // 6250 (warp per row)

    k_zero<<<256, T>>>();                                    // 1
    k_hist16<<<1024, T>>>((const float4*)att);               // 2
    k_qscan<<<1, 1024>>>();                                  // 3
    k_colledge<<<1024, T>>>((const float4*)att, src, dst);   // 4 (profiled)
    k_select<<<1, 256>>>(src, dst);                          // 5
    k_degcsr<<<49, T>>>();                                   // 6
    k_scatterx<<<eb, T>>>(att, src, dst, (const float2*)x);  // 7

    k_stage<1><<<sb, T>>>((const float2*)x, (float2*)out);   // 8
    k_stage<2><<<sb, T>>>((const float2*)x, (float2*)out);   // 9
    k_stage<3><<<sb, T>>>((const float2*)x, (float2*)out);   // 10
    k_stage<4><<<sb, T>>>((const float2*)x, (float2*)out);   // 11
}